// round 8
// baseline (speedup 1.0000x reference)
#include <cuda_runtime.h>

#define FULL 0xffffffffu

constexpr int cN = 20000;
constexpr int cE = 160000;
constexpr int cNB = cE / 256;   // 625 blocks, exact

// ---------------- device scratch (allocation-free rule: __device__ globals) ----
__device__ float g_W2[64 * 4096];                 // W2[i][k*64+o] = memw_w[(o*64+i)*64+k]
__device__ float g_U[(size_t)cN * 4096];          // 327 MB: U[x][k*64+o]
__device__ float g_S[cN * 16];                    // scores S[x][m*4+h]
__device__ float g_Pv[(size_t)cN * 256];          // Pv[x][h*64+o]
__device__ float g_q[4 * 64];                     // q_m
__device__ float g_Scls[16];
__device__ float g_Ssep[16];
__device__ float g_Pvcls[4 * 256];
__device__ float g_Pvsep[256];
__device__ float g_mememb[(size_t)cE * 64];       // per-edge mem_emb
__device__ float g_membN[cN * 64];                // per-node self mem_emb
__device__ float g_selfmsg[cN * 64];
__device__ float g_agg[cN * 64];
__device__ float g_deg[cN];
__device__ int   g_blkcnt[cNB * 8];
__device__ int   g_blkoff[cNB * 8];
__device__ int   g_estart[8];
__device__ int   g_ecnt[8];
__device__ int   g_rankblk[cE];
__device__ int   g_srccnt[cN];
__device__ int   g_rowptr[cN];
__device__ int   g_cursor[cN];
__device__ int   g_ebysrc[cE];

struct Params {
    const float* feat; const int* src; const int* dst; const int* etype;
    const float* cls_w; const float* sep;
    const float* in_w;  const float* in_b;
    const float* out_w; const float* out_b;
    const float* ln1_g; const float* ln1_b;
    const float* ln2_g; const float* ln2_b;
    const float* ff1_w; const float* ff1_b;
    const float* ff2_w; const float* ff2_b;
    const float* memcat_w; const float* memcat_b;
    const float* memw_w; const float* h_bias;
    const float* lnw_g; const float* lnw_b;
};

__device__ __forceinline__ float warpsum(float v) {
    v += __shfl_xor_sync(FULL, v, 16);
    v += __shfl_xor_sync(FULL, v, 8);
    v += __shfl_xor_sync(FULL, v, 4);
    v += __shfl_xor_sync(FULL, v, 2);
    v += __shfl_xor_sync(FULL, v, 1);
    return v;
}

// ---------------- zero state that is accumulated into -------------------------
__global__ void k_zero() {
    int i = blockIdx.x * 256 + threadIdx.x;      // grid covers cN*64 exactly
    g_agg[i] = 0.f;
    if (i < cN) { g_srccnt[i] = 0; g_cursor[i] = 0; g_deg[i] = 0.f; }
}

// ---------------- constants derived from the fixed tokens ---------------------
__global__ void k_const(Params p) {
    __shared__ float ksep[64], vsep[64], kcls[256], vcls[256];
    int t = threadIdx.x;           // 256
    int m = t >> 6, j = t & 63;
    {
        float aq = p.in_b[j], ak = p.in_b[64 + j], av = p.in_b[128 + j];
        for (int i = 0; i < 64; i++) {
            float c = p.cls_w[m * 64 + i];
            aq += p.in_w[j * 64 + i] * c;
            ak += p.in_w[(64 + j) * 64 + i] * c;
            av += p.in_w[(128 + j) * 64 + i] * c;
        }
        g_q[t] = aq; kcls[t] = ak; vcls[t] = av;
    }
    if (t < 64) {
        float ak = p.in_b[64 + t], av = p.in_b[128 + t];
        for (int i = 0; i < 64; i++) {
            float s = p.sep[i];
            ak += p.in_w[(64 + t) * 64 + i] * s;
            av += p.in_w[(128 + t) * 64 + i] * s;
        }
        ksep[t] = ak; vsep[t] = av;
    }
    __syncthreads();
    if (t < 16) {
        int mm = t >> 2, h = t & 3;
        float sc = 0.f, ss = 0.f;
        for (int jj = 0; jj < 16; jj++) {
            float q = g_q[mm * 64 + h * 16 + jj];
            sc += q * kcls[mm * 64 + h * 16 + jj];
            ss += q * ksep[h * 16 + jj];
        }
        g_Scls[t] = sc * 0.25f;   // /sqrt(16)
        g_Ssep[t] = ss * 0.25f;
    }
    {
        int h = t >> 6, o = t & 63;
        float a = 0.f;
        for (int jj = 0; jj < 16; jj++) a += p.out_w[o * 64 + h * 16 + jj] * vsep[h * 16 + jj];
        g_Pvsep[t] = a;
        for (int mm = 0; mm < 4; mm++) {
            float b = 0.f;
            for (int jj = 0; jj < 16; jj++) b += p.out_w[o * 64 + h * 16 + jj] * vcls[mm * 64 + h * 16 + jj];
            g_Pvcls[mm * 256 + t] = b;
        }
    }
}

// ---------------- per-node S and Pv -------------------------------------------
__global__ void k_node_pre(Params p) {
    __shared__ float sm[8][192];  // per warp: feat[0:64] k[64:128] v[128:192]
    int t = threadIdx.x;
    int w = t >> 5, lane = t & 31;
    int x = blockIdx.x * 8 + w;
    float* f  = sm[w];
    float* kk = f + 64;
    float* vv = f + 128;
    f[lane]      = p.feat[x * 64 + lane];
    f[lane + 32] = p.feat[x * 64 + lane + 32];
    __syncwarp();
    for (int u = 0; u < 2; u++) {
        int j = lane + 32 * u;
        float ak = p.in_b[64 + j], av = p.in_b[128 + j];
        for (int i = 0; i < 64; i++) {
            float fv = f[i];
            ak += p.in_w[(64 + j) * 64 + i] * fv;
            av += p.in_w[(128 + j) * 64 + i] * fv;
        }
        kk[j] = ak; vv[j] = av;
    }
    __syncwarp();
    if (lane < 16) {
        int mm = lane >> 2, h = lane & 3;
        float s = 0.f;
        for (int jj = 0; jj < 16; jj++) s += g_q[mm * 64 + h * 16 + jj] * kk[h * 16 + jj];
        g_S[x * 16 + lane] = s * 0.25f;
    }
    for (int u = 0; u < 8; u++) {
        int pidx = lane + 32 * u;
        int h = pidx >> 6, o = pidx & 63;
        float a = 0.f;
        for (int jj = 0; jj < 16; jj++) a += p.out_w[o * 64 + h * 16 + jj] * vv[h * 16 + jj];
        g_Pv[(size_t)x * 256 + pidx] = a;
    }
}

// ---------------- memw transpose + U GEMM -------------------------------------
__global__ void k_w2(const float* memw) {
    int idx = blockIdx.x * 256 + threadIdx.x;    // 262144 exact
    int i = idx >> 12, ko = idx & 4095, k = ko >> 6, o = ko & 63;
    g_W2[idx] = memw[(o * 64 + i) * 64 + k];
}

__global__ __launch_bounds__(256) void k_gemm(const float* feat) {
    __shared__ float As[64][65];
    __shared__ float Bs[64][64];
    int t = threadIdx.x;
    int row0 = blockIdx.y * 64;
    int col0 = blockIdx.x * 64;
    for (int l = 0; l < 16; l++) {
        int e = t + l * 256, r = e >> 6, c = e & 63;
        As[r][c] = (row0 + r < cN) ? feat[(row0 + r) * 64 + c] : 0.f;
        Bs[r][c] = g_W2[r * 4096 + col0 + c];
    }
    __syncthreads();
    int tx = t & 15, ty = t >> 4;
    float acc[4][4] = {};
    for (int k = 0; k < 64; k++) {
        float a[4], b[4];
#pragma unroll
        for (int u = 0; u < 4; u++) a[u] = As[ty + 16 * u][k];
#pragma unroll
        for (int w2 = 0; w2 < 4; w2++) b[w2] = Bs[k][tx + 16 * w2];
#pragma unroll
        for (int u = 0; u < 4; u++)
#pragma unroll
            for (int w2 = 0; w2 < 4; w2++) acc[u][w2] += a[u] * b[w2];
    }
    for (int u = 0; u < 4; u++) {
        int r = row0 + ty + 16 * u;
        if (r < cN)
            for (int w2 = 0; w2 < 4; w2++)
                g_U[(size_t)r * 4096 + col0 + tx + 16 * w2] = acc[u][w2];
    }
}

// ---------------- stable etype ordering ---------------------------------------
__global__ void k_hist(const int* etype) {
    __shared__ int wcnt[8][8];
    int t = threadIdx.x, w = t >> 5, lane = t & 31;
    int e = blockIdx.x * 256 + t;                // exact, no tail
    int et = etype[e];
    unsigned mask = __match_any_sync(FULL, et);
    int rw = __popc(mask & ((1u << lane) - 1u));
    for (int r = 0; r < 5; r++) {
        unsigned b = __ballot_sync(FULL, et == r);
        if (lane == 0) wcnt[w][r] = __popc(b);
    }
    __syncthreads();
    int off = 0;
    for (int ww = 0; ww < w; ww++) off += wcnt[ww][et];
    g_rankblk[e] = rw + off;
    if (t < 5) {
        int s = 0;
        for (int ww = 0; ww < 8; ww++) s += wcnt[ww][t];
        g_blkcnt[blockIdx.x * 8 + t] = s;
    }
}

__global__ void k_scanE() {
    int t = threadIdx.x;
    if (t < 5) {
        int run = 0;
        for (int b0 = 0; b0 < cNB; b0 += 25) {   // 625 = 25*25
            int c[25];
#pragma unroll
            for (int u = 0; u < 25; u++) c[u] = g_blkcnt[(b0 + u) * 8 + t];
#pragma unroll
            for (int u = 0; u < 25; u++) { g_blkoff[(b0 + u) * 8 + t] = run; run += c[u]; }
        }
        g_ecnt[t] = run;
    }
    __syncthreads();
    if (t == 0) {
        int s = 0;
        for (int r = 0; r < 5; r++) { g_estart[r] = s; s += g_ecnt[r]; }
    }
}

// ---------------- CSR by src + dst degrees ------------------------------------
__global__ void k_count(const int* src, const int* dst) {
    int e = blockIdx.x * 256 + threadIdx.x;
    atomicAdd(&g_srccnt[src[e]], 1);
    atomicAdd(&g_deg[dst[e]], 1.0f);
}

__global__ void k_scanS() {
    const int CH = 20;                           // 1024*20 >= 20000
    int t = threadIdx.x;
    int base = t * CH;
    int loc[CH]; int s = 0;
#pragma unroll
    for (int i = 0; i < CH; i++) {
        int idx = base + i;
        int c = (idx < cN) ? g_srccnt[idx] : 0;
        loc[i] = s; s += c;
    }
    int lane = t & 31, w = t >> 5;
    int v = s;
    for (int off = 1; off < 32; off <<= 1) {
        int n = __shfl_up_sync(FULL, v, off);
        if (lane >= off) v += n;
    }
    __shared__ int wsum[32];
    if (lane == 31) wsum[w] = v;
    __syncthreads();
    if (w == 0) {
        int vv = wsum[lane];
        for (int off = 1; off < 32; off <<= 1) {
            int n = __shfl_up_sync(FULL, vv, off);
            if (lane >= off) vv += n;
        }
        wsum[lane] = vv;
    }
    __syncthreads();
    int excl = v - s + (w > 0 ? wsum[w - 1] : 0);
    for (int i = 0; i < CH; i++) {
        int idx = base + i;
        if (idx < cN) g_rowptr[idx] = excl + loc[i];
    }
}

__global__ void k_fill(const int* src) {
    int e = blockIdx.x * 256 + threadIdx.x;
    int s = src[e];
    int slot = g_rowptr[s] + atomicAdd(&g_cursor[s], 1);
    g_ebysrc[slot] = e;
}

// ---------------- the factorized encoder (one warp per pair) ------------------
template <bool WCAT>
__device__ __forceinline__ void encode_pair(
    const Params& p, int lane, int a, int b, float* ys,
    float& me0, float& me1,
    float* catbase, float* labbase, long pos0, int posStride)
{
    int d0 = lane, d1 = lane + 32;
    float pva[4][2], pvb[4][2], pvs[4][2];
    const float* Pa = g_Pv + (size_t)a * 256;
    const float* Pb = g_Pv + (size_t)b * 256;
#pragma unroll
    for (int h = 0; h < 4; h++) {
        pva[h][0] = Pa[h * 64 + d0]; pva[h][1] = Pa[h * 64 + d1];
        pvb[h][0] = Pb[h * 64 + d0]; pvb[h][1] = Pb[h * 64 + d1];
        pvs[h][0] = g_Pvsep[h * 64 + d0]; pvs[h][1] = g_Pvsep[h * 64 + d1];
    }
    const float* Sa = g_S + a * 16;
    const float* Sb = g_S + b * 16;
    float ob0 = p.out_b[d0], ob1 = p.out_b[d1];
    me0 = 0.f; me1 = 0.f;
    for (int m = 0; m < 4; m++) {
        float o0 = ob0, o1 = ob1;
#pragma unroll
        for (int h = 0; h < 4; h++) {
            float s0 = g_Scls[m * 4 + h], s1 = Sa[m * 4 + h];
            float s2 = g_Ssep[m * 4 + h], s3 = Sb[m * 4 + h];
            float mx = fmaxf(fmaxf(s0, s1), fmaxf(s2, s3));
            float e0 = __expf(s0 - mx), e1 = __expf(s1 - mx);
            float e2 = __expf(s2 - mx), e3 = __expf(s3 - mx);
            float inv = 1.f / (e0 + e1 + e2 + e3);
            e0 *= inv; e1 *= inv; e2 *= inv; e3 *= inv;
            float pc0 = g_Pvcls[m * 256 + h * 64 + d0];
            float pc1 = g_Pvcls[m * 256 + h * 64 + d1];
            o0 += e0 * pc0 + e1 * pva[h][0] + e2 * pvs[h][0] + e3 * pvb[h][0];
            o1 += e0 * pc1 + e1 * pva[h][1] + e2 * pvs[h][1] + e3 * pvb[h][1];
        }
        float x0 = p.cls_w[m * 64 + d0] + o0;
        float x1 = p.cls_w[m * 64 + d1] + o1;
        // LN1
        float mean = warpsum(x0 + x1) * (1.f / 64.f);
        float c0 = x0 - mean, c1 = x1 - mean;
        float var = warpsum(c0 * c0 + c1 * c1) * (1.f / 64.f);
        float rs = rsqrtf(var + 1e-5f);
        float y0 = c0 * rs * p.ln1_g[d0] + p.ln1_b[d0];
        float y1 = c1 * rs * p.ln1_g[d1] + p.ln1_b[d1];
        // FF (16 hidden), split lanes 0..15 / 16..31 over the 64-dim reduction
        ys[d0] = y0; ys[d1] = y1;
        __syncwarp();
        int j = lane & 15, half = lane >> 4;
        float acc = half ? 0.f : p.ff1_b[j];
        int dbase = half * 32;
#pragma unroll 8
        for (int dd = 0; dd < 32; dd++) {
            int d = dbase + dd;
            acc += ys[d] * p.ff1_w[j * 64 + d];
        }
        acc += __shfl_down_sync(FULL, acc, 16);
        float z = fmaxf(acc, 0.f);               // valid on lanes 0..15
        float f0 = p.ff2_b[d0], f1 = p.ff2_b[d1];
#pragma unroll
        for (int jj = 0; jj < 16; jj++) {
            float zj = __shfl_sync(FULL, z, jj);
            f0 += zj * p.ff2_w[d0 * 16 + jj];
            f1 += zj * p.ff2_w[d1 * 16 + jj];
        }
        __syncwarp();                            // ys reused next m
        float x20 = y0 + f0, x21 = y1 + f1;
        // LN2
        float mean2 = warpsum(x20 + x21) * (1.f / 64.f);
        float e20 = x20 - mean2, e21 = x21 - mean2;
        float var2 = warpsum(e20 * e20 + e21 * e21) * (1.f / 64.f);
        float rs2 = rsqrtf(var2 + 1e-5f);
        float t0 = e20 * rs2 * p.ln2_g[d0] + p.ln2_b[d0];
        float t1 = e21 * rs2 * p.ln2_g[d1] + p.ln2_b[d1];
        me0 += t0; me1 += t1;
        if (WCAT) {
            long pos = pos0 + (long)m * posStride;
            float cv[4];
#pragma unroll
            for (int c = 0; c < 4; c++) {
                float pv = t0 * p.memcat_w[c * 64 + d0] + t1 * p.memcat_w[c * 64 + d1];
                cv[c] = warpsum(pv);
            }
            if (lane == 0) {
                float* row = catbase + pos * 4;
                row[0] = cv[0] + p.memcat_b[0];
                row[1] = cv[1] + p.memcat_b[1];
                row[2] = cv[2] + p.memcat_b[2];
                row[3] = cv[3] + p.memcat_b[3];
                labbase[pos] = (float)m;
            }
        }
    }
}

__global__ void k_edge(Params p, float* catbase, float* labbase) {
    __shared__ float ysm[8][64];
    int t = threadIdx.x, w = t >> 5, lane = t & 31;
    int e = blockIdx.x * 8 + w;                  // exact: 20000*8
    int a = p.src[e], b = p.dst[e];
    int et = p.etype[e];
    int local = g_blkoff[(e >> 8) * 8 + et] + g_rankblk[e];
    long pos0 = 4L * g_estart[et] + local;
    int stride = g_ecnt[et];
    float me0, me1;
    encode_pair<true>(p, lane, a, b, ysm[w], me0, me1, catbase, labbase, pos0, stride);
    g_mememb[(size_t)e * 64 + lane]      = me0;
    g_mememb[(size_t)e * 64 + lane + 32] = me1;
}

__global__ void k_self(Params p) {
    __shared__ float ysm[8][64];
    int t = threadIdx.x, w = t >> 5, lane = t & 31;
    int x = blockIdx.x * 8 + w;                  // exact: 2500*8
    float me0, me1;
    encode_pair<false>(p, lane, x, x, ysm[w], me0, me1, nullptr, nullptr, 0, 0);
    g_membN[x * 64 + lane]      = me0;
    g_membN[x * 64 + lane + 32] = me1;
}

// ---------------- messages: U[x] staged once in SMEM --------------------------
__global__ void k_msg(const int* dst) {
    __shared__ float Us[4096];
    int t = threadIdx.x;
    int x = blockIdx.x;
    size_t ub = (size_t)x * 4096;
    for (int l = 0; l < 16; l++) Us[t + l * 256] = g_U[ub + t + l * 256];
    __syncthreads();
    int o = t & 63, g = t >> 6;
    if (g == 0) {                                 // self-loop message
        const float* mb = g_membN + x * 64;
        float acc = 0.f;
#pragma unroll 8
        for (int k = 0; k < 64; k++) acc += mb[k] * Us[k * 64 + o];
        g_selfmsg[x * 64 + o] = acc;
    }
    int nE = g_srccnt[x];
    int base = g_rowptr[x];
    for (int jj = g; jj < nE; jj += 4) {
        int e = g_ebysrc[base + jj];
        const float* mb = g_mememb + (size_t)e * 64;
        float acc = 0.f;
#pragma unroll 8
        for (int k = 0; k < 64; k++) acc += mb[k] * Us[k * 64 + o];
        atomicAdd(&g_agg[dst[e] * 64 + o], acc);
    }
}

// ---------------- final node update -------------------------------------------
__global__ void k_final(Params p, float* out) {
    int t = threadIdx.x, w = t >> 5, lane = t & 31;
    int x = blockIdx.x * 8 + w;                  // exact
    int d0 = lane, d1 = lane + 32;
    float inv = 1.f / fmaxf(g_deg[x], 1.f);
    float a0 = g_agg[x * 64 + d0] * inv;
    float a1 = g_agg[x * 64 + d1] * inv;
    float mean = warpsum(a0 + a1) * (1.f / 64.f);
    float c0 = a0 - mean, c1 = a1 - mean;
    float var = warpsum(c0 * c0 + c1 * c1) * (1.f / 64.f);
    float rs = rsqrtf(var + 1e-5f);
    float v0 = c0 * rs * p.lnw_g[d0] + p.lnw_b[d0] + p.h_bias[d0] + g_selfmsg[x * 64 + d0];
    float v1 = c1 * rs * p.lnw_g[d1] + p.lnw_b[d1] + p.h_bias[d1] + g_selfmsg[x * 64 + d1];
    v0 = v0 > 0.f ? v0 : 0.2f * v0;
    v1 = v1 > 0.f ? v1 : 0.2f * v1;
    out[x * 64 + d0] = v0;
    out[x * 64 + d1] = v1;
}

extern "C" void kernel_launch(void* const* d_in, const int* in_sizes, int n_in,
                              void* d_out, int out_size) {
    Params p;
    p.feat  = (const float*)d_in[0];
    p.src   = (const int*)d_in[1];
    p.dst   = (const int*)d_in[2];
    p.etype = (const int*)d_in[3];
    p.cls_w = (const float*)d_in[4];
    p.sep   = (const float*)d_in[5];
    p.in_w  = (const float*)d_in[6];
    p.in_b  = (const float*)d_in[7];
    p.out_w = (const float*)d_in[8];
    p.out_b = (const float*)d_in[9];
    p.ln1_g = (const float*)d_in[10];
    p.ln1_b = (const float*)d_in[11];
    p.ln2_g = (const float*)d_in[12];
    p.ln2_b = (const float*)d_in[13];
    p.ff1_w = (const float*)d_in[14];
    p.ff1_b = (const float*)d_in[15];
    p.ff2_w = (const float*)d_in[16];
    p.ff2_b = (const float*)d_in[17];
    p.memcat_w = (const float*)d_in[18];
    p.memcat_b = (const float*)d_in[19];
    p.memw_w   = (const float*)d_in[20];
    p.h_bias   = (const float*)d_in[21];
    p.lnw_g    = (const float*)d_in[22];
    p.lnw_b    = (const float*)d_in[23];

    float* out  = (float*)d_out;
    float* catb = out + (size_t)cN * 64;                 // 1,280,000
    float* labb = catb + (size_t)4 * cE * 4;             // +2,560,000

    k_zero<<<cN * 64 / 256, 256>>>();
    k_const<<<1, 256>>>(p);
    k_w2<<<64 * 4096 / 256, 256>>>(p.memw_w);
    k_node_pre<<<cN / 8, 256>>>(p);
    dim3 gg(64, (cN + 63) / 64);
    k_gemm<<<gg, 256>>>(p.feat);
    k_hist<<<cNB, 256>>>(p.etype);
    k_scanE<<<1, 32>>>();
    k_count<<<cE / 256, 256>>>(p.src, p.dst);
    k_scanS<<<1, 1024>>>();
    k_fill<<<cE / 256, 256>>>(p.src);
    k_edge<<<cE / 8, 256>>>(p, catb, labb);
    k_self<<<cN / 8, 256>>>(p);
    k_msg<<<cN, 256>>>(p.dst);
    k_final<<<cN / 8, 256>>>(p, out);
}

// round 9
// speedup vs baseline: 4.4714x; 4.4714x over previous
#include <cuda_runtime.h>

#define FULL 0xffffffffu

constexpr int cN = 20000;
constexpr int cE = 160000;
constexpr int cNB = cE / 256;   // 625 blocks, exact

// ---------------- device scratch (allocation-free rule: __device__ globals) ----
__device__ float g_W2[64 * 4096];                 // W2[i][k*64+o] = memw_w[(o*64+i)*64+k]
__device__ float g_U[(size_t)cN * 4096];          // 327 MB: U[x][k*64+o]
__device__ float g_S[cN * 16];                    // scores S[x][m*4+h]
__device__ float g_Pv[(size_t)cN * 256];          // Pv[x][h*64+o]
__device__ float g_q[4 * 64];                     // q_m
__device__ float g_Scls[16];
__device__ float g_Ssep[16];
__device__ float g_Pvcls[4 * 256];
__device__ float g_Pvsep[256];
// fused per-node precompute tables
__device__ float g_Ct[64 * 256];                  // Ct[i][h*64+o] = sum_jj out_w[o,h16+jj]*in_w[128+h16+jj, i]
__device__ float g_Dt[64 * 16];                   // Dt[i][m*4+h]
__device__ float g_Pvb[256];
__device__ float g_Sb[16];
__device__ float g_mememb[(size_t)cE * 64];       // per-edge mem_emb
__device__ float g_membN[cN * 64];                // per-node self mem_emb
__device__ float g_selfmsg[cN * 64];
__device__ float g_agg[cN * 64];
__device__ float g_deg[cN];
__device__ int   g_blkcnt[cNB * 8];
__device__ int   g_blkoff[cNB * 8];
__device__ int   g_estart[8];
__device__ int   g_ecnt[8];
__device__ int   g_rankblk[cE];
__device__ int   g_srccnt[cN];
__device__ int   g_rowptr[cN];
__device__ int   g_cursor[cN];
__device__ int   g_ebysrc[cE];

struct Params {
    const float* feat; const int* src; const int* dst; const int* etype;
    const float* cls_w; const float* sep;
    const float* in_w;  const float* in_b;
    const float* out_w; const float* out_b;
    const float* ln1_g; const float* ln1_b;
    const float* ln2_g; const float* ln2_b;
    const float* ff1_w; const float* ff1_b;
    const float* ff2_w; const float* ff2_b;
    const float* memcat_w; const float* memcat_b;
    const float* memw_w; const float* h_bias;
    const float* lnw_g; const float* lnw_b;
};

__device__ __forceinline__ float warpsum(float v) {
    v += __shfl_xor_sync(FULL, v, 16);
    v += __shfl_xor_sync(FULL, v, 8);
    v += __shfl_xor_sync(FULL, v, 4);
    v += __shfl_xor_sync(FULL, v, 2);
    v += __shfl_xor_sync(FULL, v, 1);
    return v;
}

// ---------------- zero state that is accumulated into -------------------------
__global__ void k_zero() {
    int i = blockIdx.x * 256 + threadIdx.x;      // grid covers cN*64 exactly
    g_agg[i] = 0.f;
    if (i < cN) { g_srccnt[i] = 0; g_cursor[i] = 0; g_deg[i] = 0.f; }
}

// ---------------- constants derived from the fixed tokens ---------------------
__global__ void k_const(Params p) {
    __shared__ float ksep[64], vsep[64], kcls[256], vcls[256];
    int t = threadIdx.x;           // 256
    int m = t >> 6, j = t & 63;
    {
        float aq = p.in_b[j], ak = p.in_b[64 + j], av = p.in_b[128 + j];
        for (int i = 0; i < 64; i++) {
            float c = p.cls_w[m * 64 + i];
            aq += p.in_w[j * 64 + i] * c;
            ak += p.in_w[(64 + j) * 64 + i] * c;
            av += p.in_w[(128 + j) * 64 + i] * c;
        }
        g_q[t] = aq; kcls[t] = ak; vcls[t] = av;
    }
    if (t < 64) {
        float ak = p.in_b[64 + t], av = p.in_b[128 + t];
        for (int i = 0; i < 64; i++) {
            float s = p.sep[i];
            ak += p.in_w[(64 + t) * 64 + i] * s;
            av += p.in_w[(128 + t) * 64 + i] * s;
        }
        ksep[t] = ak; vsep[t] = av;
    }
    __syncthreads();
    if (t < 16) {
        int mm = t >> 2, h = t & 3;
        float sc = 0.f, ss = 0.f;
        for (int jj = 0; jj < 16; jj++) {
            float q = g_q[mm * 64 + h * 16 + jj];
            sc += q * kcls[mm * 64 + h * 16 + jj];
            ss += q * ksep[h * 16 + jj];
        }
        g_Scls[t] = sc * 0.25f;   // /sqrt(16)
        g_Ssep[t] = ss * 0.25f;
    }
    {
        int h = t >> 6, o = t & 63;
        float a = 0.f;
        for (int jj = 0; jj < 16; jj++) a += p.out_w[o * 64 + h * 16 + jj] * vsep[h * 16 + jj];
        g_Pvsep[t] = a;
        for (int mm = 0; mm < 4; mm++) {
            float b = 0.f;
            for (int jj = 0; jj < 16; jj++) b += p.out_w[o * 64 + h * 16 + jj] * vcls[mm * 64 + h * 16 + jj];
            g_Pvcls[mm * 256 + t] = b;
        }
    }
}

// ---------------- fused per-node tables: Ct, Dt, Pvb, Sb ----------------------
__global__ void k_fuse(Params p) {
    int bb = blockIdx.x, t = threadIdx.x;
    if (bb < 64) {
        int idx = bb * 256 + t;                  // 16384
        int ip = idx >> 8, pp = idx & 255, h = pp >> 6, o = pp & 63;
        float acc = 0.f;
        for (int jj = 0; jj < 16; jj++)
            acc += p.out_w[o * 64 + h * 16 + jj] * p.in_w[(128 + h * 16 + jj) * 64 + ip];
        g_Ct[idx] = acc;
    } else if (bb == 64) {
        for (int r = 0; r < 4; r++) {
            int idx = r * 256 + t;               // 1024
            int ip = idx >> 4, mh = idx & 15, m = mh >> 2, h = mh & 3;
            float acc = 0.f;
            for (int jj = 0; jj < 16; jj++)
                acc += g_q[m * 64 + h * 16 + jj] * p.in_w[(64 + h * 16 + jj) * 64 + ip];
            g_Dt[idx] = acc * 0.25f;
        }
    } else {
        int h = t >> 6, o = t & 63;
        float acc = 0.f;
        for (int jj = 0; jj < 16; jj++)
            acc += p.out_w[o * 64 + h * 16 + jj] * p.in_b[128 + h * 16 + jj];
        g_Pvb[t] = acc;
        if (t < 16) {
            int m = t >> 2, h2 = t & 3;
            float a2 = 0.f;
            for (int jj = 0; jj < 16; jj++)
                a2 += g_q[m * 64 + h2 * 16 + jj] * p.in_b[64 + h2 * 16 + jj];
            g_Sb[t] = a2 * 0.25f;
        }
    }
}

// ---------------- per-node S and Pv (coalesced, L1-resident Ct/Dt) ------------
__global__ __launch_bounds__(256) void k_node_pre(const float* feat) {
    __shared__ float fb[8][64];
    int t = threadIdx.x, w = t >> 5, lane = t & 31;
    int x = blockIdx.x * 8 + w;                  // grid cN/8
    fb[w][lane]      = feat[x * 64 + lane];
    fb[w][lane + 32] = feat[x * 64 + lane + 32];
    __syncwarp();
    float acc[8];
#pragma unroll
    for (int u = 0; u < 8; u++) acc[u] = g_Pvb[lane + 32 * u];
    float s = (lane < 16) ? g_Sb[lane] : 0.f;
    for (int i = 0; i < 64; i++) {
        float fv = fb[w][i];
#pragma unroll
        for (int u = 0; u < 8; u++) acc[u] += g_Ct[i * 256 + lane + 32 * u] * fv;
        if (lane < 16) s += g_Dt[i * 16 + lane] * fv;
    }
    size_t base = (size_t)x * 256;
#pragma unroll
    for (int u = 0; u < 8; u++) g_Pv[base + lane + 32 * u] = acc[u];
    if (lane < 16) g_S[x * 16 + lane] = s;
}

// ---------------- memw transpose + U GEMM -------------------------------------
__global__ void k_w2(const float* memw) {
    int idx = blockIdx.x * 256 + threadIdx.x;    // 262144 exact
    int i = idx >> 12, ko = idx & 4095, k = ko >> 6, o = ko & 63;
    g_W2[idx] = memw[(o * 64 + i) * 64 + k];
}

// 128x64 output tile, 256 threads, 8x4 register tile, K=64 single slab.
__global__ __launch_bounds__(256) void k_gemm(const float* feat) {
    __shared__ float As[128 * 64];               // row-major [r][k]
    __shared__ float Bs[64 * 64];                // [k][c]
    int t = threadIdx.x;
    int row0 = blockIdx.y * 128;
    int col0 = blockIdx.x * 64;
    for (int l = 0; l < 32; l++) {
        int e = t + l * 256; int r = e >> 6, c = e & 63;
        As[e] = (row0 + r < cN) ? feat[(row0 + r) * 64 + c] : 0.f;
    }
    for (int l = 0; l < 16; l++) {
        int e = t + l * 256; int r = e >> 6, c = e & 63;
        Bs[e] = g_W2[r * 4096 + col0 + c];
    }
    __syncthreads();
    int tx = t & 15, ty = t >> 4;
    int ra = ty * 8, cb = tx * 4;
    float acc[8][4] = {};
    for (int k4 = 0; k4 < 64; k4 += 4) {
        float4 av[8];
#pragma unroll
        for (int u = 0; u < 8; u++) av[u] = *(const float4*)&As[(ra + u) * 64 + k4];
        float4 bv[4];
#pragma unroll
        for (int kk = 0; kk < 4; kk++) bv[kk] = *(const float4*)&Bs[(k4 + kk) * 64 + cb];
#pragma unroll
        for (int u = 0; u < 8; u++) {
            acc[u][0] += av[u].x * bv[0].x + av[u].y * bv[1].x + av[u].z * bv[2].x + av[u].w * bv[3].x;
            acc[u][1] += av[u].x * bv[0].y + av[u].y * bv[1].y + av[u].z * bv[2].y + av[u].w * bv[3].y;
            acc[u][2] += av[u].x * bv[0].z + av[u].y * bv[1].z + av[u].z * bv[2].z + av[u].w * bv[3].z;
            acc[u][3] += av[u].x * bv[0].w + av[u].y * bv[1].w + av[u].z * bv[2].w + av[u].w * bv[3].w;
        }
    }
#pragma unroll
    for (int u = 0; u < 8; u++) {
        int r = row0 + ra + u;
        if (r < cN)
            *(float4*)&g_U[(size_t)r * 4096 + col0 + cb] =
                make_float4(acc[u][0], acc[u][1], acc[u][2], acc[u][3]);
    }
}

// ---------------- stable etype ordering ---------------------------------------
__global__ void k_hist(const int* etype) {
    __shared__ int wcnt[8][8];
    int t = threadIdx.x, w = t >> 5, lane = t & 31;
    int e = blockIdx.x * 256 + t;                // exact, no tail
    int et = etype[e];
    unsigned mask = __match_any_sync(FULL, et);
    int rw = __popc(mask & ((1u << lane) - 1u));
    for (int r = 0; r < 5; r++) {
        unsigned b = __ballot_sync(FULL, et == r);
        if (lane == 0) wcnt[w][r] = __popc(b);
    }
    __syncthreads();
    int off = 0;
    for (int ww = 0; ww < w; ww++) off += wcnt[ww][et];
    g_rankblk[e] = rw + off;
    if (t < 5) {
        int s = 0;
        for (int ww = 0; ww < 8; ww++) s += wcnt[ww][t];
        g_blkcnt[blockIdx.x * 8 + t] = s;
    }
}

__global__ void k_scanE() {
    int t = threadIdx.x;
    if (t < 5) {
        int run = 0;
        for (int b0 = 0; b0 < cNB; b0 += 25) {   // 625 = 25*25
            int c[25];
#pragma unroll
            for (int u = 0; u < 25; u++) c[u] = g_blkcnt[(b0 + u) * 8 + t];
#pragma unroll
            for (int u = 0; u < 25; u++) { g_blkoff[(b0 + u) * 8 + t] = run; run += c[u]; }
        }
        g_ecnt[t] = run;
    }
    __syncthreads();
    if (t == 0) {
        int s = 0;
        for (int r = 0; r < 5; r++) { g_estart[r] = s; s += g_ecnt[r]; }
    }
}

// ---------------- CSR by src + dst degrees ------------------------------------
__global__ void k_count(const int* src, const int* dst) {
    int e = blockIdx.x * 256 + threadIdx.x;
    atomicAdd(&g_srccnt[src[e]], 1);
    atomicAdd(&g_deg[dst[e]], 1.0f);
}

__global__ void k_scanS() {
    const int CH = 20;                           // 1024*20 >= 20000
    int t = threadIdx.x;
    int base = t * CH;
    int loc[CH]; int s = 0;
#pragma unroll
    for (int i = 0; i < CH; i++) {
        int idx = base + i;
        int c = (idx < cN) ? g_srccnt[idx] : 0;
        loc[i] = s; s += c;
    }
    int lane = t & 31, w = t >> 5;
    int v = s;
    for (int off = 1; off < 32; off <<= 1) {
        int n = __shfl_up_sync(FULL, v, off);
        if (lane >= off) v += n;
    }
    __shared__ int wsum[32];
    if (lane == 31) wsum[w] = v;
    __syncthreads();
    if (w == 0) {
        int vv = wsum[lane];
        for (int off = 1; off < 32; off <<= 1) {
            int n = __shfl_up_sync(FULL, vv, off);
            if (lane >= off) vv += n;
        }
        wsum[lane] = vv;
    }
    __syncthreads();
    int excl = v - s + (w > 0 ? wsum[w - 1] : 0);
    for (int i = 0; i < CH; i++) {
        int idx = base + i;
        if (idx < cN) g_rowptr[idx] = excl + loc[i];
    }
}

__global__ void k_fill(const int* src) {
    int e = blockIdx.x * 256 + threadIdx.x;
    int s = src[e];
    int slot = g_rowptr[s] + atomicAdd(&g_cursor[s], 1);
    g_ebysrc[slot] = e;
}

// ---------------- shared-staged encoder constants ------------------------------
// layout in cs[]:
constexpr int FF1o = 0;      // [dd*32 + lane] = ff1_w[(lane&15)*64 + (lane>>4)*32 + dd]  (1024)
constexpr int FF2o = 1024;   // [jj*64 + d]    = ff2_w[d*16 + jj]                         (1024)
constexpr int MCWo = 2048;   // memcat_w                                                  (256)
constexpr int PVCo = 2304;   // g_Pvcls                                                   (1024)
constexpr int PVSo = 3328;   // g_Pvsep                                                   (256)
constexpr int SCLo = 3584;   // g_Scls                                                    (16)
constexpr int SSEo = 3600;   // g_Ssep                                                    (16)
constexpr int CLSo = 3616;   // cls_w                                                     (256)
constexpr int CS_TOT = 3872;

__device__ __forceinline__ void stage_consts(const Params& p, float* cs, int t) {
    for (int l = 0; l < 4; l++) {
        int i = t + l * 256;                     // 1024
        int dd = i >> 5, hl = i & 31;
        cs[FF1o + i] = p.ff1_w[(hl & 15) * 64 + (hl >> 4) * 32 + dd];
        int d = i >> 4, jj = i & 15;
        cs[FF2o + jj * 64 + d] = p.ff2_w[i];
        cs[PVCo + i] = g_Pvcls[i];
    }
    cs[MCWo + t] = p.memcat_w[t];
    cs[CLSo + t] = p.cls_w[t];
    if (t < 256) cs[PVSo + t] = g_Pvsep[t];
    if (t < 16) { cs[SCLo + t] = g_Scls[t]; cs[SSEo + t] = g_Ssep[t]; }
}

// ---------------- the factorized encoder (one warp per pair) ------------------
template <bool WCAT>
__device__ __forceinline__ void encode_pair(
    const Params& p, const float* cs, int lane, int a, int b, float* ys,
    float& me0, float& me1,
    float* catbase, float* labbase, long pos0, int posStride)
{
    int d0 = lane, d1 = lane + 32;
    float pva[4][2], pvb[4][2];
    const float* Pa = g_Pv + (size_t)a * 256;
    const float* Pb = g_Pv + (size_t)b * 256;
#pragma unroll
    for (int h = 0; h < 4; h++) {
        pva[h][0] = Pa[h * 64 + d0]; pva[h][1] = Pa[h * 64 + d1];
        pvb[h][0] = Pb[h * 64 + d0]; pvb[h][1] = Pb[h * 64 + d1];
    }
    const float* Sa = g_S + a * 16;
    const float* Sb2 = g_S + b * 16;
    float ob0 = p.out_b[d0], ob1 = p.out_b[d1];
    float l1g0 = p.ln1_g[d0], l1g1 = p.ln1_g[d1];
    float l1b0 = p.ln1_b[d0], l1b1 = p.ln1_b[d1];
    float l2g0 = p.ln2_g[d0], l2g1 = p.ln2_g[d1];
    float l2b0 = p.ln2_b[d0], l2b1 = p.ln2_b[d1];
    float f2b0 = p.ff2_b[d0], f2b1 = p.ff2_b[d1];
    int j = lane & 15, half = lane >> 4;
    float f1b = half ? 0.f : p.ff1_b[j];
    int dbase = half * 32;
    me0 = 0.f; me1 = 0.f;
    for (int m = 0; m < 4; m++) {
        float o0 = ob0, o1 = ob1;
#pragma unroll
        for (int h = 0; h < 4; h++) {
            float s0 = cs[SCLo + m * 4 + h], s1 = Sa[m * 4 + h];
            float s2 = cs[SSEo + m * 4 + h], s3 = Sb2[m * 4 + h];
            float mx = fmaxf(fmaxf(s0, s1), fmaxf(s2, s3));
            float e0 = __expf(s0 - mx), e1 = __expf(s1 - mx);
            float e2 = __expf(s2 - mx), e3 = __expf(s3 - mx);
            float inv = 1.f / (e0 + e1 + e2 + e3);
            e0 *= inv; e1 *= inv; e2 *= inv; e3 *= inv;
            float pc0 = cs[PVCo + m * 256 + h * 64 + d0];
            float pc1 = cs[PVCo + m * 256 + h * 64 + d1];
            float ps0 = cs[PVSo + h * 64 + d0];
            float ps1 = cs[PVSo + h * 64 + d1];
            o0 += e0 * pc0 + e1 * pva[h][0] + e2 * ps0 + e3 * pvb[h][0];
            o1 += e0 * pc1 + e1 * pva[h][1] + e2 * ps1 + e3 * pvb[h][1];
        }
        float x0 = cs[CLSo + m * 64 + d0] + o0;
        float x1 = cs[CLSo + m * 64 + d1] + o1;
        // LN1
        float mean = warpsum(x0 + x1) * (1.f / 64.f);
        float c0 = x0 - mean, c1 = x1 - mean;
        float var = warpsum(c0 * c0 + c1 * c1) * (1.f / 64.f);
        float rs = rsqrtf(var + 1e-5f);
        float y0 = c0 * rs * l1g0 + l1b0;
        float y1 = c1 * rs * l1g1 + l1b1;
        // FF (16 hidden), split lanes 0..15 / 16..31 over the 64-dim reduction
        ys[d0] = y0; ys[d1] = y1;
        __syncwarp();
        float acc = f1b;
#pragma unroll
        for (int dd = 0; dd < 32; dd++)
            acc += ys[dbase + dd] * cs[FF1o + dd * 32 + lane];
        acc += __shfl_down_sync(FULL, acc, 16);
        float z = fmaxf(acc, 0.f);               // valid on lanes 0..15
        float f0 = f2b0, f1v = f2b1;
#pragma unroll
        for (int jj = 0; jj < 16; jj++) {
            float zj = __shfl_sync(FULL, z, jj);
            f0 += zj * cs[FF2o + jj * 64 + d0];
            f1v += zj * cs[FF2o + jj * 64 + d1];
        }
        __syncwarp();                            // ys reused next m
        float x20 = y0 + f0, x21 = y1 + f1v;
        // LN2
        float mean2 = warpsum(x20 + x21) * (1.f / 64.f);
        float e20 = x20 - mean2, e21 = x21 - mean2;
        float var2 = warpsum(e20 * e20 + e21 * e21) * (1.f / 64.f);
        float rs2 = rsqrtf(var2 + 1e-5f);
        float t0 = e20 * rs2 * l2g0 + l2b0;
        float t1 = e21 * rs2 * l2g1 + l2b1;
        me0 += t0; me1 += t1;
        if (WCAT) {
            long pos = pos0 + (long)m * posStride;
            float cv[4];
#pragma unroll
            for (int c = 0; c < 4; c++) {
                float pv = t0 * cs[MCWo + c * 64 + d0] + t1 * cs[MCWo + c * 64 + d1];
                cv[c] = warpsum(pv);
            }
            if (lane == 0) {
                float* row = catbase + pos * 4;
                row[0] = cv[0] + p.memcat_b[0];
                row[1] = cv[1] + p.memcat_b[1];
                row[2] = cv[2] + p.memcat_b[2];
                row[3] = cv[3] + p.memcat_b[3];
                labbase[pos] = (float)m;
            }
        }
    }
}

__global__ __launch_bounds__(256) void k_edge(Params p, float* catbase, float* labbase) {
    __shared__ float cs[CS_TOT];
    __shared__ float ysm[8][64];
    int t = threadIdx.x, w = t >> 5, lane = t & 31;
    stage_consts(p, cs, t);
    __syncthreads();
    int e = blockIdx.x * 8 + w;                  // exact: 20000*8
    int a = p.src[e], b = p.dst[e];
    int et = p.etype[e];
    int local = g_blkoff[(e >> 8) * 8 + et] + g_rankblk[e];
    long pos0 = 4L * g_estart[et] + local;
    int stride = g_ecnt[et];
    float me0, me1;
    encode_pair<true>(p, cs, lane, a, b, ysm[w], me0, me1, catbase, labbase, pos0, stride);
    g_mememb[(size_t)e * 64 + lane]      = me0;
    g_mememb[(size_t)e * 64 + lane + 32] = me1;
}

__global__ __launch_bounds__(256) void k_self(Params p) {
    __shared__ float cs[CS_TOT];
    __shared__ float ysm[8][64];
    int t = threadIdx.x, w = t >> 5, lane = t & 31;
    stage_consts(p, cs, t);
    __syncthreads();
    int x = blockIdx.x * 8 + w;                  // exact: 2500*8
    float me0, me1;
    encode_pair<false>(p, cs, lane, x, x, ysm[w], me0, me1, nullptr, nullptr, 0, 0);
    g_membN[x * 64 + lane]      = me0;
    g_membN[x * 64 + lane + 32] = me1;
}

// ---------------- messages: U[x] staged once in SMEM --------------------------
__global__ void k_msg(const int* dst) {
    __shared__ float Us[4096];
    int t = threadIdx.x;
    int x = blockIdx.x;
    {
        const float4* U4 = (const float4*)(g_U + (size_t)x * 4096);
        float4* Us4 = (float4*)Us;
        for (int l = 0; l < 4; l++) Us4[t + l * 256] = U4[t + l * 256];
    }
    __syncthreads();
    int o = t & 63, g = t >> 6;
    if (g == 0) {                                 // self-loop message
        const float4* mb = (const float4*)(g_membN + x * 64);
        float acc = 0.f;
#pragma unroll
        for (int k4 = 0; k4 < 16; k4++) {
            float4 m4 = mb[k4];
            acc += m4.x * Us[(k4 * 4 + 0) * 64 + o] + m4.y * Us[(k4 * 4 + 1) * 64 + o]
                 + m4.z * Us[(k4 * 4 + 2) * 64 + o] + m4.w * Us[(k4 * 4 + 3) * 64 + o];
        }
        g_selfmsg[x * 64 + o] = acc;
    }
    int nE = g_srccnt[x];
    int base = g_rowptr[x];
    for (int jj = g; jj < nE; jj += 4) {
        int e = g_ebysrc[base + jj];
        const float4* mb = (const float4*)(g_mememb + (size_t)e * 64);
        float acc = 0.f;
#pragma unroll 4
        for (int k4 = 0; k4 < 16; k4++) {
            float4 m4 = mb[k4];
            acc += m4.x * Us[(k4 * 4 + 0) * 64 + o] + m4.y * Us[(k4 * 4 + 1) * 64 + o]
                 + m4.z * Us[(k4 * 4 + 2) * 64 + o] + m4.w * Us[(k4 * 4 + 3) * 64 + o];
        }
        atomicAdd(&g_agg[dst[e] * 64 + o], acc);
    }
}

// ---------------- final node update -------------------------------------------
__global__ void k_final(Params p, float* out) {
    int t = threadIdx.x, w = t >> 5, lane = t & 31;
    int x = blockIdx.x * 8 + w;                  // exact
    int d0 = lane, d1 = lane + 32;
    float inv = 1.f / fmaxf(g_deg[x], 1.f);
    float a0 = g_agg[x * 64 + d0] * inv;
    float a1 = g_agg[x * 64 + d1] * inv;
    float mean = warpsum(a0 + a1) * (1.f / 64.f);
    float c0 = a0 - mean, c1 = a1 - mean;
    float var = warpsum(c0 * c0 + c1 * c1) * (1.f / 64.f);
    float rs = rsqrtf(var + 1e-5f);
    float v0 = c0 * rs * p.lnw_g[d0] + p.lnw_b[d0] + p.h_bias[d0] + g_selfmsg[x * 64 + d0];
    float v1 = c1 * rs * p.lnw_g[d1] + p.lnw_b[d1] + p.h_bias[d1] + g_selfmsg[x * 64 + d1];
    v0 = v0 > 0.f ? v0 : 0.2f * v0;
    v1 = v1 > 0.f ? v1 : 0.2f * v1;
    out[x * 64 + d0] = v0;
    out[x * 64 + d1] = v1;
}

extern "C" void kernel_launch(void* const* d_in, const int* in_sizes, int n_in,
                              void* d_out, int out_size) {
    Params p;
    p.feat  = (const float*)d_in[0];
    p.src   = (const int*)d_in[1];
    p.dst   = (const int*)d_in[2];
    p.etype = (const int*)d_in[3];
    p.cls_w = (const float*)d_in[4];
    p.sep   = (const float*)d_in[5];
    p.in_w  = (const float*)d_in[6];
    p.in_b  = (const float*)d_in[7];
    p.out_w = (const float*)d_in[8];
    p.out_b = (const float*)d_in[9];
    p.ln1_g = (const float*)d_in[10];
    p.ln1_b = (const float*)d_in[11];
    p.ln2_g = (const float*)d_in[12];
    p.ln2_b = (const float*)d_in[13];
    p.ff1_w = (const float*)d_in[14];
    p.ff1_b = (const float*)d_in[15];
    p.ff2_w = (const float*)d_in[16];
    p.ff2_b = (const float*)d_in[17];
    p.memcat_w = (const float*)d_in[18];
    p.memcat_b = (const float*)d_in[19];
    p.memw_w   = (const float*)d_in[20];
    p.h_bias   = (const float*)d_in[21];
    p.lnw_g    = (const float*)d_in[22];
    p.lnw_b    = (const float*)d_in[23];

    float* out  = (float*)d_out;
    float* catb = out + (size_t)cN * 64;                 // 1,280,000
    float* labb = catb + (size_t)4 * cE * 4;             // +2,560,000

    k_zero<<<cN * 64 / 256, 256>>>();
    k_const<<<1, 256>>>(p);
    k_fuse<<<66, 256>>>(p);
    k_w2<<<64 * 4096 / 256, 256>>>(p.memw_w);
    k_node_pre<<<cN / 8, 256>>>(p.feat);
    dim3 gg(4096 / 64, (cN + 127) / 128);
    k_gemm<<<gg, 256>>>(p.feat);
    k_hist<<<cNB, 256>>>(p.etype);
    k_scanE<<<1, 32>>>();
    k_count<<<cE / 256, 256>>>(p.src, p.dst);
    k_scanS<<<1, 1024>>>();
    k_fill<<<cE / 256, 256>>>(p.src);
    k_edge<<<cE / 8, 256>>>(p, catb, labb);
    k_self<<<cN / 8, 256>>>(p);
    k_msg<<<cN, 256>>>(p.dst);
    k_final<<<cN / 8, 256>>>(p, out);
}

// round 10
// speedup vs baseline: 4.8424x; 1.0830x over previous
#include <cuda_runtime.h>

#define FULL 0xffffffffu

constexpr int cN = 20000;
constexpr int cE = 160000;
constexpr int cNB = cE / 256;   // 625 blocks, exact

// ---------------- device scratch (allocation-free rule: __device__ globals) ----
__device__ float g_W2[64 * 4096];                 // W2[i][k*64+o] = memw_w[(o*64+i)*64+k]
__device__ float g_U[(size_t)cN * 4096];          // 327 MB: U[x][k*64+o]
__device__ float g_S[cN * 16];                    // scores S[x][m*4+h]
__device__ float g_Pv[(size_t)cN * 256];          // Pv[x][h*64+o]
__device__ float g_q[4 * 64];                     // q_m
__device__ float g_Scls[16];
__device__ float g_Ssep[16];
__device__ float g_Pvcls[4 * 256];
__device__ float g_Pvsep[256];
// fused per-node precompute tables
__device__ float g_Ct[64 * 256];                  // Ct[i][h*64+o]
__device__ float g_Dt[64 * 16];                   // Dt[i][m*4+h]
__device__ float g_Pvb[256];
__device__ float g_Sb[16];
__device__ float g_mememb[(size_t)cE * 64];       // per-edge mem_emb
__device__ float g_membN[cN * 64];                // per-node self mem_emb
__device__ float g_selfmsg[cN * 64];
__device__ float g_agg[cN * 64];
__device__ float g_deg[cN];
__device__ int   g_blkcnt[cNB * 8];
__device__ int   g_blkoff[cNB * 8];
__device__ int   g_estart[8];
__device__ int   g_ecnt[8];
__device__ int   g_rankblk[cE];
__device__ int   g_srccnt[cN];
__device__ int   g_rowptr[cN];
__device__ int   g_cursor[cN];
__device__ int   g_ebysrc[cE];

struct Params {
    const float* feat; const int* src; const int* dst; const int* etype;
    const float* cls_w; const float* sep;
    const float* in_w;  const float* in_b;
    const float* out_w; const float* out_b;
    const float* ln1_g; const float* ln1_b;
    const float* ln2_g; const float* ln2_b;
    const float* ff1_w; const float* ff1_b;
    const float* ff2_w; const float* ff2_b;
    const float* memcat_w; const float* memcat_b;
    const float* memw_w; const float* h_bias;
    const float* lnw_g; const float* lnw_b;
};

__device__ __forceinline__ float warpsum(float v) {
    v += __shfl_xor_sync(FULL, v, 16);
    v += __shfl_xor_sync(FULL, v, 8);
    v += __shfl_xor_sync(FULL, v, 4);
    v += __shfl_xor_sync(FULL, v, 2);
    v += __shfl_xor_sync(FULL, v, 1);
    return v;
}

// ---------------- zero state that is accumulated into -------------------------
__global__ void k_zero() {
    int i = blockIdx.x * 256 + threadIdx.x;      // grid covers cN*64 exactly
    g_agg[i] = 0.f;
    if (i < cN) { g_srccnt[i] = 0; g_cursor[i] = 0; g_deg[i] = 0.f; }
}

// ---------------- constants derived from the fixed tokens ---------------------
__global__ void k_const(Params p) {
    __shared__ float ksep[64], vsep[64], kcls[256], vcls[256];
    int t = threadIdx.x;           // 256
    int m = t >> 6, j = t & 63;
    {
        float aq = p.in_b[j], ak = p.in_b[64 + j], av = p.in_b[128 + j];
        for (int i = 0; i < 64; i++) {
            float c = p.cls_w[m * 64 + i];
            aq += p.in_w[j * 64 + i] * c;
            ak += p.in_w[(64 + j) * 64 + i] * c;
            av += p.in_w[(128 + j) * 64 + i] * c;
        }
        g_q[t] = aq; kcls[t] = ak; vcls[t] = av;
    }
    if (t < 64) {
        float ak = p.in_b[64 + t], av = p.in_b[128 + t];
        for (int i = 0; i < 64; i++) {
            float s = p.sep[i];
            ak += p.in_w[(64 + t) * 64 + i] * s;
            av += p.in_w[(128 + t) * 64 + i] * s;
        }
        ksep[t] = ak; vsep[t] = av;
    }
    __syncthreads();
    if (t < 16) {
        int mm = t >> 2, h = t & 3;
        float sc = 0.f, ss = 0.f;
        for (int jj = 0; jj < 16; jj++) {
            float q = g_q[mm * 64 + h * 16 + jj];
            sc += q * kcls[mm * 64 + h * 16 + jj];
            ss += q * ksep[h * 16 + jj];
        }
        g_Scls[t] = sc * 0.25f;   // /sqrt(16)
        g_Ssep[t] = ss * 0.25f;
    }
    {
        int h = t >> 6, o = t & 63;
        float a = 0.f;
        for (int jj = 0; jj < 16; jj++) a += p.out_w[o * 64 + h * 16 + jj] * vsep[h * 16 + jj];
        g_Pvsep[t] = a;
        for (int mm = 0; mm < 4; mm++) {
            float b = 0.f;
            for (int jj = 0; jj < 16; jj++) b += p.out_w[o * 64 + h * 16 + jj] * vcls[mm * 64 + h * 16 + jj];
            g_Pvcls[mm * 256 + t] = b;
        }
    }
}

// ---------------- fused per-node tables: Ct, Dt, Pvb, Sb ----------------------
__global__ void k_fuse(Params p) {
    int bb = blockIdx.x, t = threadIdx.x;
    if (bb < 64) {
        int idx = bb * 256 + t;                  // 16384
        int ip = idx >> 8, pp = idx & 255, h = pp >> 6, o = pp & 63;
        float acc = 0.f;
        for (int jj = 0; jj < 16; jj++)
            acc += p.out_w[o * 64 + h * 16 + jj] * p.in_w[(128 + h * 16 + jj) * 64 + ip];
        g_Ct[idx] = acc;
    } else if (bb == 64) {
        for (int r = 0; r < 4; r++) {
            int idx = r * 256 + t;               // 1024
            int ip = idx >> 4, mh = idx & 15, m = mh >> 2, h = mh & 3;
            float acc = 0.f;
            for (int jj = 0; jj < 16; jj++)
                acc += g_q[m * 64 + h * 16 + jj] * p.in_w[(64 + h * 16 + jj) * 64 + ip];
            g_Dt[idx] = acc * 0.25f;
        }
    } else {
        int h = t >> 6, o = t & 63;
        float acc = 0.f;
        for (int jj = 0; jj < 16; jj++)
            acc += p.out_w[o * 64 + h * 16 + jj] * p.in_b[128 + h * 16 + jj];
        g_Pvb[t] = acc;
        if (t < 16) {
            int m = t >> 2, h2 = t & 3;
            float a2 = 0.f;
            for (int jj = 0; jj < 16; jj++)
                a2 += g_q[m * 64 + h2 * 16 + jj] * p.in_b[64 + h2 * 16 + jj];
            g_Sb[t] = a2 * 0.25f;
        }
    }
}

// ---------------- per-node S and Pv (float4 LSU path) -------------------------
__global__ __launch_bounds__(256) void k_node_pre(const float* feat) {
    __shared__ float fb[8][64];
    int t = threadIdx.x, w = t >> 5, lane = t & 31;
    int x = blockIdx.x * 8 + w;                  // grid cN/8
    fb[w][lane]      = feat[x * 64 + lane];
    fb[w][lane + 32] = feat[x * 64 + lane + 32];
    __syncwarp();
    const float4* Pvb4 = (const float4*)g_Pvb;
    float4 a0 = Pvb4[lane * 2];
    float4 a1 = Pvb4[lane * 2 + 1];
    float s = (lane < 16) ? g_Sb[lane] : 0.f;
    for (int i = 0; i < 64; i++) {
        float fv = fb[w][i];
        const float4* C4 = (const float4*)(g_Ct + i * 256);
        float4 c0 = C4[lane * 2], c1 = C4[lane * 2 + 1];
        a0.x += c0.x * fv; a0.y += c0.y * fv; a0.z += c0.z * fv; a0.w += c0.w * fv;
        a1.x += c1.x * fv; a1.y += c1.y * fv; a1.z += c1.z * fv; a1.w += c1.w * fv;
        if (lane < 16) s += g_Dt[i * 16 + lane] * fv;
    }
    float4* P4 = (float4*)(g_Pv + (size_t)x * 256);
    P4[lane * 2] = a0; P4[lane * 2 + 1] = a1;
    if (lane < 16) g_S[x * 16 + lane] = s;
}

// ---------------- memw transpose + U GEMM -------------------------------------
__global__ void k_w2(const float* memw) {
    int idx = blockIdx.x * 256 + threadIdx.x;    // 262144 exact
    int i = idx >> 12, ko = idx & 4095, k = ko >> 6, o = ko & 63;
    g_W2[idx] = memw[(o * 64 + i) * 64 + k];
}

// 128x64 output tile, 256 threads, 8x4 register tile, K=64 single slab.
__global__ __launch_bounds__(256) void k_gemm(const float* feat) {
    __shared__ float As[128 * 64];               // row-major [r][k]
    __shared__ float Bs[64 * 64];                // [k][c]
    int t = threadIdx.x;
    int row0 = blockIdx.y * 128;
    int col0 = blockIdx.x * 64;
    for (int l = 0; l < 32; l++) {
        int e = t + l * 256; int r = e >> 6, c = e & 63;
        As[e] = (row0 + r < cN) ? feat[(row0 + r) * 64 + c] : 0.f;
    }
    for (int l = 0; l < 16; l++) {
        int e = t + l * 256; int r = e >> 6, c = e & 63;
        Bs[e] = g_W2[r * 4096 + col0 + c];
    }
    __syncthreads();
    int tx = t & 15, ty = t >> 4;
    int ra = ty * 8, cb = tx * 4;
    float acc[8][4] = {};
    for (int k4 = 0; k4 < 64; k4 += 4) {
        float4 av[8];
#pragma unroll
        for (int u = 0; u < 8; u++) av[u] = *(const float4*)&As[(ra + u) * 64 + k4];
        float4 bv[4];
#pragma unroll
        for (int kk = 0; kk < 4; kk++) bv[kk] = *(const float4*)&Bs[(k4 + kk) * 64 + cb];
#pragma unroll
        for (int u = 0; u < 8; u++) {
            acc[u][0] += av[u].x * bv[0].x + av[u].y * bv[1].x + av[u].z * bv[2].x + av[u].w * bv[3].x;
            acc[u][1] += av[u].x * bv[0].y + av[u].y * bv[1].y + av[u].z * bv[2].y + av[u].w * bv[3].y;
            acc[u][2] += av[u].x * bv[0].z + av[u].y * bv[1].z + av[u].z * bv[2].z + av[u].w * bv[3].z;
            acc[u][3] += av[u].x * bv[0].w + av[u].y * bv[1].w + av[u].z * bv[2].w + av[u].w * bv[3].w;
        }
    }
#pragma unroll
    for (int u = 0; u < 8; u++) {
        int r = row0 + ra + u;
        if (r < cN)
            *(float4*)&g_U[(size_t)r * 4096 + col0 + cb] =
                make_float4(acc[u][0], acc[u][1], acc[u][2], acc[u][3]);
    }
}

// ---------------- stable etype ordering ---------------------------------------
__global__ void k_hist(const int* etype) {
    __shared__ int wcnt[8][8];
    int t = threadIdx.x, w = t >> 5, lane = t & 31;
    int e = blockIdx.x * 256 + t;                // exact, no tail
    int et = etype[e];
    unsigned mask = __match_any_sync(FULL, et);
    int rw = __popc(mask & ((1u << lane) - 1u));
    for (int r = 0; r < 5; r++) {
        unsigned b = __ballot_sync(FULL, et == r);
        if (lane == 0) wcnt[w][r] = __popc(b);
    }
    __syncthreads();
    int off = 0;
    for (int ww = 0; ww < w; ww++) off += wcnt[ww][et];
    g_rankblk[e] = rw + off;
    if (t < 5) {
        int s = 0;
        for (int ww = 0; ww < 8; ww++) s += wcnt[ww][t];
        g_blkcnt[blockIdx.x * 8 + t] = s;
    }
}

__global__ void k_scanE() {
    int t = threadIdx.x;
    if (t < 5) {
        int run = 0;
        for (int b0 = 0; b0 < cNB; b0 += 25) {   // 625 = 25*25
            int c[25];
#pragma unroll
            for (int u = 0; u < 25; u++) c[u] = g_blkcnt[(b0 + u) * 8 + t];
#pragma unroll
            for (int u = 0; u < 25; u++) { g_blkoff[(b0 + u) * 8 + t] = run; run += c[u]; }
        }
        g_ecnt[t] = run;
    }
    __syncthreads();
    if (t == 0) {
        int s = 0;
        for (int r = 0; r < 5; r++) { g_estart[r] = s; s += g_ecnt[r]; }
    }
}

// ---------------- CSR by src + dst degrees ------------------------------------
__global__ void k_count(const int* src, const int* dst) {
    int e = blockIdx.x * 256 + threadIdx.x;
    atomicAdd(&g_srccnt[src[e]], 1);
    atomicAdd(&g_deg[dst[e]], 1.0f);
}

__global__ void k_scanS() {
    const int CH = 20;                           // 1024*20 >= 20000
    int t = threadIdx.x;
    int base = t * CH;
    int loc[CH]; int s = 0;
#pragma unroll
    for (int i = 0; i < CH; i++) {
        int idx = base + i;
        int c = (idx < cN) ? g_srccnt[idx] : 0;
        loc[i] = s; s += c;
    }
    int lane = t & 31, w = t >> 5;
    int v = s;
    for (int off = 1; off < 32; off <<= 1) {
        int n = __shfl_up_sync(FULL, v, off);
        if (lane >= off) v += n;
    }
    __shared__ int wsum[32];
    if (lane == 31) wsum[w] = v;
    __syncthreads();
    if (w == 0) {
        int vv = wsum[lane];
        for (int off = 1; off < 32; off <<= 1) {
            int n = __shfl_up_sync(FULL, vv, off);
            if (lane >= off) vv += n;
        }
        wsum[lane] = vv;
    }
    __syncthreads();
    int excl = v - s + (w > 0 ? wsum[w - 1] : 0);
    for (int i = 0; i < CH; i++) {
        int idx = base + i;
        if (idx < cN) g_rowptr[idx] = excl + loc[i];
    }
}

__global__ void k_fill(const int* src) {
    int e = blockIdx.x * 256 + threadIdx.x;
    int s = src[e];
    int slot = g_rowptr[s] + atomicAdd(&g_cursor[s], 1);
    g_ebysrc[slot] = e;
}

// ---------------- shared-staged encoder constants ------------------------------
constexpr int FF1o = 0;      // [dd*32 + lane]                                            (1024)
constexpr int FF2o = 1024;   // [jj*64 + d]                                               (1024)
constexpr int MCWo = 2048;   // memcat_w                                                  (256)
constexpr int PVCo = 2304;   // g_Pvcls                                                   (1024)
constexpr int PVSo = 3328;   // g_Pvsep                                                   (256)
constexpr int SCLo = 3584;   // g_Scls                                                    (16)
constexpr int SSEo = 3600;   // g_Ssep                                                    (16)
constexpr int CLSo = 3616;   // cls_w                                                     (256)
constexpr int CS_TOT = 3872;

__device__ __forceinline__ void stage_consts(const Params& p, float* cs, int t) {
    for (int l = 0; l < 4; l++) {
        int i = t + l * 256;                     // 1024
        int dd = i >> 5, hl = i & 31;
        cs[FF1o + i] = p.ff1_w[(hl & 15) * 64 + (hl >> 4) * 32 + dd];
        int d = i >> 4, jj = i & 15;
        cs[FF2o + jj * 64 + d] = p.ff2_w[i];
        cs[PVCo + i] = g_Pvcls[i];
    }
    cs[MCWo + t] = p.memcat_w[t];
    cs[CLSo + t] = p.cls_w[t];
    if (t < 256) cs[PVSo + t] = g_Pvsep[t];
    if (t < 16) { cs[SCLo + t] = g_Scls[t]; cs[SSEo + t] = g_Ssep[t]; }
}

// lane-indexed constants hoisted out of the per-edge loop
struct LaneConst {
    float ob0, ob1, l1g0, l1g1, l1b0, l1b1, l2g0, l2g1, l2b0, l2b1, f2b0, f2b1, f1b;
};

__device__ __forceinline__ LaneConst load_lane_const(const Params& p, int lane) {
    LaneConst L;
    int d0 = lane, d1 = lane + 32;
    L.ob0 = p.out_b[d0];  L.ob1 = p.out_b[d1];
    L.l1g0 = p.ln1_g[d0]; L.l1g1 = p.ln1_g[d1];
    L.l1b0 = p.ln1_b[d0]; L.l1b1 = p.ln1_b[d1];
    L.l2g0 = p.ln2_g[d0]; L.l2g1 = p.ln2_g[d1];
    L.l2b0 = p.ln2_b[d0]; L.l2b1 = p.ln2_b[d1];
    L.f2b0 = p.ff2_b[d0]; L.f2b1 = p.ff2_b[d1];
    L.f1b = (lane >> 4) ? 0.f : p.ff1_b[lane & 15];
    return L;
}

// ---------------- the factorized encoder (one warp per pair) ------------------
// Softmax weights computed once on lanes 0..15, broadcast via per-warp SMEM.
template <bool WCAT>
__device__ __forceinline__ void encode_pair(
    const float* cs, int lane, int a, int b, float* ys, float* es,
    const LaneConst& L, float& me0, float& me1,
    float* catbase, float* labbase, long pos0, int posStride,
    float mb0, float mb1, float mb2, float mb3)
{
    int d0 = lane, d1 = lane + 32;
    if (lane < 16) {
        float s0 = cs[SCLo + lane], s1 = g_S[a * 16 + lane];
        float s2 = cs[SSEo + lane], s3 = g_S[b * 16 + lane];
        float mx = fmaxf(fmaxf(s0, s1), fmaxf(s2, s3));
        float e0 = __expf(s0 - mx), e1 = __expf(s1 - mx);
        float e2 = __expf(s2 - mx), e3 = __expf(s3 - mx);
        float inv = 1.f / (e0 + e1 + e2 + e3);
        ((float4*)es)[lane] = make_float4(e0 * inv, e1 * inv, e2 * inv, e3 * inv);
    }
    float pva[4][2], pvb[4][2];
    const float* Pa = g_Pv + (size_t)a * 256;
    const float* Pb = g_Pv + (size_t)b * 256;
#pragma unroll
    for (int h = 0; h < 4; h++) {
        pva[h][0] = Pa[h * 64 + d0]; pva[h][1] = Pa[h * 64 + d1];
        pvb[h][0] = Pb[h * 64 + d0]; pvb[h][1] = Pb[h * 64 + d1];
    }
    __syncwarp();
    me0 = 0.f; me1 = 0.f;
    int dbase = (lane >> 4) * 32;
    for (int m = 0; m < 4; m++) {
        float o0 = L.ob0, o1 = L.ob1;
#pragma unroll
        for (int h = 0; h < 4; h++) {
            float4 ev = ((const float4*)es)[m * 4 + h];   // broadcast LDS.128
            float pc0 = cs[PVCo + m * 256 + h * 64 + d0];
            float pc1 = cs[PVCo + m * 256 + h * 64 + d1];
            float ps0 = cs[PVSo + h * 64 + d0];
            float ps1 = cs[PVSo + h * 64 + d1];
            o0 += ev.x * pc0 + ev.y * pva[h][0] + ev.z * ps0 + ev.w * pvb[h][0];
            o1 += ev.x * pc1 + ev.y * pva[h][1] + ev.z * ps1 + ev.w * pvb[h][1];
        }
        float x0 = cs[CLSo + m * 64 + d0] + o0;
        float x1 = cs[CLSo + m * 64 + d1] + o1;
        // LN1
        float mean = warpsum(x0 + x1) * (1.f / 64.f);
        float c0 = x0 - mean, c1 = x1 - mean;
        float var = warpsum(c0 * c0 + c1 * c1) * (1.f / 64.f);
        float rs = rsqrtf(var + 1e-5f);
        float y0 = c0 * rs * L.l1g0 + L.l1b0;
        float y1 = c1 * rs * L.l1g1 + L.l1b1;
        // FF (16 hidden), split lanes 0..15 / 16..31 over the 64-dim reduction
        ys[d0] = y0; ys[d1] = y1;
        __syncwarp();
        float acc = L.f1b;
#pragma unroll
        for (int dd = 0; dd < 32; dd++)
            acc += ys[dbase + dd] * cs[FF1o + dd * 32 + lane];
        acc += __shfl_down_sync(FULL, acc, 16);
        float z = fmaxf(acc, 0.f);               // valid on lanes 0..15
        float f0 = L.f2b0, f1v = L.f2b1;
#pragma unroll
        for (int jj = 0; jj < 16; jj++) {
            float zj = __shfl_sync(FULL, z, jj);
            f0 += zj * cs[FF2o + jj * 64 + d0];
            f1v += zj * cs[FF2o + jj * 64 + d1];
        }
        __syncwarp();                            // ys reused next m
        float x20 = y0 + f0, x21 = y1 + f1v;
        // LN2
        float mean2 = warpsum(x20 + x21) * (1.f / 64.f);
        float e20 = x20 - mean2, e21 = x21 - mean2;
        float var2 = warpsum(e20 * e20 + e21 * e21) * (1.f / 64.f);
        float rs2 = rsqrtf(var2 + 1e-5f);
        float t0 = e20 * rs2 * L.l2g0 + L.l2b0;
        float t1 = e21 * rs2 * L.l2g1 + L.l2b1;
        me0 += t0; me1 += t1;
        if (WCAT) {
            long pos = pos0 + (long)m * posStride;
            float cv[4];
#pragma unroll
            for (int c = 0; c < 4; c++) {
                float pv = t0 * cs[MCWo + c * 64 + d0] + t1 * cs[MCWo + c * 64 + d1];
                cv[c] = warpsum(pv);
            }
            if (lane == 0) {
                *(float4*)(catbase + pos * 4) =
                    make_float4(cv[0] + mb0, cv[1] + mb1, cv[2] + mb2, cv[3] + mb3);
                labbase[pos] = (float)m;
            }
        }
    }
}

__global__ __launch_bounds__(256) void k_edge(Params p, float* catbase, float* labbase) {
    __shared__ float cs[CS_TOT];
    __shared__ float ysm[8][64];
    __shared__ float esm[8][64];
    int t = threadIdx.x, w = t >> 5, lane = t & 31;
    stage_consts(p, cs, t);
    LaneConst L = load_lane_const(p, lane);
    float mb0 = p.memcat_b[0], mb1 = p.memcat_b[1];
    float mb2 = p.memcat_b[2], mb3 = p.memcat_b[3];
    __syncthreads();
    int step = gridDim.x * 8;
    for (int e = blockIdx.x * 8 + w; e < cE; e += step) {
        int a = p.src[e], b = p.dst[e];
        int et = p.etype[e];
        int local = g_blkoff[(e >> 8) * 8 + et] + g_rankblk[e];
        long pos0 = 4L * g_estart[et] + local;
        int stride = g_ecnt[et];
        float me0, me1;
        encode_pair<true>(cs, lane, a, b, ysm[w], esm[w], L, me0, me1,
                          catbase, labbase, pos0, stride, mb0, mb1, mb2, mb3);
        g_mememb[(size_t)e * 64 + lane]      = me0;
        g_mememb[(size_t)e * 64 + lane + 32] = me1;
    }
}

__global__ __launch_bounds__(256) void k_self(Params p) {
    __shared__ float cs[CS_TOT];
    __shared__ float ysm[8][64];
    __shared__ float esm[8][64];
    int t = threadIdx.x, w = t >> 5, lane = t & 31;
    stage_consts(p, cs, t);
    LaneConst L = load_lane_const(p, lane);
    __syncthreads();
    int step = gridDim.x * 8;
    for (int x = blockIdx.x * 8 + w; x < cN; x += step) {
        float me0, me1;
        encode_pair<false>(cs, lane, x, x, ysm[w], esm[w], L, me0, me1,
                           nullptr, nullptr, 0, 0, 0.f, 0.f, 0.f, 0.f);
        g_membN[x * 64 + lane]      = me0;
        g_membN[x * 64 + lane + 32] = me1;
    }
}

// ---------------- messages: U[x] staged once in SMEM --------------------------
__global__ void k_msg(const int* dst) {
    __shared__ float Us[4096];
    int t = threadIdx.x;
    int x = blockIdx.x;
    {
        const float4* U4 = (const float4*)(g_U + (size_t)x * 4096);
        float4* Us4 = (float4*)Us;
        for (int l = 0; l < 4; l++) Us4[t + l * 256] = U4[t + l * 256];
    }
    __syncthreads();
    int o = t & 63, g = t >> 6;
    if (g == 0) {                                 // self-loop message
        const float4* mb = (const float4*)(g_membN + x * 64);
        float acc = 0.f;
#pragma unroll
        for (int k4 = 0; k4 < 16; k4++) {
            float4 m4 = mb[k4];
            acc += m4.x * Us[(k4 * 4 + 0) * 64 + o] + m4.y * Us[(k4 * 4 + 1) * 64 + o]
                 + m4.z * Us[(k4 * 4 + 2) * 64 + o] + m4.w * Us[(k4 * 4 + 3) * 64 + o];
        }
        g_selfmsg[x * 64 + o] = acc;
    }
    int nE = g_srccnt[x];
    int base = g_rowptr[x];
    for (int jj = g; jj < nE; jj += 4) {
        int e = g_ebysrc[base + jj];
        const float4* mb = (const float4*)(g_mememb + (size_t)e * 64);
        float acc = 0.f;
#pragma unroll 4
        for (int k4 = 0; k4 < 16; k4++) {
            float4 m4 = mb[k4];
            acc += m4.x * Us[(k4 * 4 + 0) * 64 + o] + m4.y * Us[(k4 * 4 + 1) * 64 + o]
                 + m4.z * Us[(k4 * 4 + 2) * 64 + o] + m4.w * Us[(k4 * 4 + 3) * 64 + o];
        }
        atomicAdd(&g_agg[dst[e] * 64 + o], acc);
    }
}

// ---------------- final node update -------------------------------------------
__global__ void k_final(Params p, float* out) {
    int t = threadIdx.x, w = t >> 5, lane = t & 31;
    int x = blockIdx.x * 8 + w;                  // exact
    int d0 = lane, d1 = lane + 32;
    float inv = 1.f / fmaxf(g_deg[x], 1.f);
    float a0 = g_agg[x * 64 + d0] * inv;
    float a1 = g_agg[x * 64 + d1] * inv;
    float mean = warpsum(a0 + a1) * (1.f / 64.f);
    float c0 = a0 - mean, c1 = a1 - mean;
    float var = warpsum(c0 * c0 + c1 * c1) * (1.f / 64.f);
    float rs = rsqrtf(var + 1e-5f);
    float v0 = c0 * rs * p.lnw_g[d0] + p.lnw_b[d0] + p.h_bias[d0] + g_selfmsg[x * 64 + d0];
    float v1 = c1 * rs * p.lnw_g[d1] + p.lnw_b[d1] + p.h_bias[d1] + g_selfmsg[x * 64 + d1];
    v0 = v0 > 0.f ? v0 : 0.2f * v0;
    v1 = v1 > 0.f ? v1 : 0.2f * v1;
    out[x * 64 + d0] = v0;
    out[x * 64 + d1] = v1;
}

extern "C" void kernel_launch(void* const* d_in, const int* in_sizes, int n_in,
                              void* d_out, int out_size) {
    Params p;
    p.feat  = (const float*)d_in[0];
    p.src   = (const int*)d_in[1];
    p.dst   = (const int*)d_in[2];
    p.etype = (const int*)d_in[3];
    p.cls_w = (const float*)d_in[4];
    p.sep   = (const float*)d_in[5];
    p.in_w  = (const float*)d_in[6];
    p.in_b  = (const float*)d_in[7];
    p.out_w = (const float*)d_in[8];
    p.out_b = (const float*)d_in[9];
    p.ln1_g = (const float*)d_in[10];
    p.ln1_b = (const float*)d_in[11];
    p.ln2_g = (const float*)d_in[12];
    p.ln2_b = (const float*)d_in[13];
    p.ff1_w = (const float*)d_in[14];
    p.ff1_b = (const float*)d_in[15];
    p.ff2_w = (const float*)d_in[16];
    p.ff2_b = (const float*)d_in[17];
    p.memcat_w = (const float*)d_in[18];
    p.memcat_b = (const float*)d_in[19];
    p.memw_w   = (const float*)d_in[20];
    p.h_bias   = (const float*)d_in[21];
    p.lnw_g    = (const float*)d_in[22];
    p.lnw_b    = (const float*)d_in[23];

    float* out  = (float*)d_out;
    float* catb = out + (size_t)cN * 64;                 // 1,280,000
    float* labb = catb + (size_t)4 * cE * 4;             // +2,560,000

    k_zero<<<cN * 64 / 256, 256>>>();
    k_const<<<1, 256>>>(p);
    k_fuse<<<66, 256>>>(p);
    k_w2<<<64 * 4096 / 256, 256>>>(p.memw_w);
    k_node_pre<<<cN / 8, 256>>>(p.feat);
    dim3 gg(4096 / 64, (cN + 127) / 128);
    k_gemm<<<gg, 256>>>(p.feat);
    k_hist<<<cNB, 256>>>(p.etype);
    k_scanE<<<1, 32>>>();
    k_count<<<cE / 256, 256>>>(p.src, p.dst);
    k_scanS<<<1, 1024>>>();
    k_fill<<<cE / 256, 256>>>(p.src);
    k_edge<<<1250, 256>>>(p, catb, labb);
    k_self<<<250, 256>>>(p);
    k_msg<<<cN, 256>>>(p.dst);
    k_final<<<cN / 8, 256>>>(p, out);
}